// round 2
// baseline (speedup 1.0000x reference)
#include <cuda_runtime.h>

#define NODES 100000
#define NEDGE 1600000

// Scratch (allocation-free rule: __device__ globals)
__device__ float  g_deg [NODES];
__device__ float  g_dinv[NODES];
__device__ float4 g_xs  [NODES];   // dinv-scaled input features (layer-1 messages)
__device__ float4 g_acc1[NODES];   // layer-1 aggregation accumulator
__device__ float4 g_gs  [NODES];   // dinv-scaled layer-2 messages (after fused MLP)
__device__ float4 g_acc2[NODES];   // layer-2 aggregation accumulator

__device__ __forceinline__ void red_add_v4(float4* addr, float4 v) {
    asm volatile("red.global.add.v4.f32 [%0], {%1,%2,%3,%4};"
                 :: "l"(addr), "f"(v.x), "f"(v.y), "f"(v.z), "f"(v.w)
                 : "memory");
}

// deg[i] = 1.0 (self loop)
__global__ void k_deg_init(int n) {
    int i = blockIdx.x * blockDim.x + threadIdx.x;
    if (i < n) g_deg[i] = 1.0f;
}

// deg[col[e]] += 1 for each edge (4 edges/thread, int4 loads)
__global__ void k_deg_count(const int* __restrict__ col, int e) {
    int t = blockIdx.x * blockDim.x + threadIdx.x;
    int base = t * 4;
    if (base + 3 < e) {
        int4 c = ((const int4*)col)[t];
        atomicAdd(&g_deg[c.x], 1.0f);
        atomicAdd(&g_deg[c.y], 1.0f);
        atomicAdd(&g_deg[c.z], 1.0f);
        atomicAdd(&g_deg[c.w], 1.0f);
    } else if (base < e) {
        for (int k = base; k < e; k++) atomicAdd(&g_deg[col[k]], 1.0f);
    }
}

// dinv = rsqrt(deg); xs = x * dinv; acc1 init = xs (self loop)
__global__ void k_node_pre(const float4* __restrict__ x, int n) {
    int i = blockIdx.x * blockDim.x + threadIdx.x;
    if (i < n) {
        float d = rsqrtf(g_deg[i]);
        g_dinv[i] = d;
        float4 v = x[i];
        v.x *= d; v.y *= d; v.z *= d; v.w *= d;
        g_xs[i]   = v;
        g_acc1[i] = v;
    }
}

// Generic 4-wide edge scatter: dst[col[e]] += src[row[e]]
__global__ void k_scatter(const int* __restrict__ row, const int* __restrict__ col,
                          const float4* __restrict__ src, float4* __restrict__ dst, int e) {
    int t = blockIdx.x * blockDim.x + threadIdx.x;
    int base = t * 4;
    if (base + 3 < e) {
        int4 r = ((const int4*)row)[t];
        int4 c = ((const int4*)col)[t];
        float4 v0 = src[r.x];
        float4 v1 = src[r.y];
        float4 v2 = src[r.z];
        float4 v3 = src[r.w];
        red_add_v4(&dst[c.x], v0);
        red_add_v4(&dst[c.y], v1);
        red_add_v4(&dst[c.z], v2);
        red_add_v4(&dst[c.w], v3);
    } else if (base < e) {
        for (int k = base; k < e; k++) red_add_v4(&dst[col[k]], src[row[k]]);
    }
}

// Fused per-node MLP: a1 = dinv*acc1; h = relu(a1@W1 + b1); g = h@W2;
// gs = g*dinv; acc2 init = gs (self loop)
__global__ void k_mlp(const float* __restrict__ W1, const float* __restrict__ b1,
                      const float* __restrict__ W2, int n) {
    __shared__ float sW1[256];  // [4][64] row-major
    __shared__ float sB1[64];
    __shared__ float sW2[256];  // [64][4] row-major
    int tid = threadIdx.x;
    if (tid < 256) { sW1[tid] = W1[tid]; sW2[tid] = W2[tid]; }
    if (tid < 64)  { sB1[tid] = b1[tid]; }
    __syncthreads();

    int i = blockIdx.x * blockDim.x + tid;
    if (i < n) {
        float d = g_dinv[i];
        float4 a = g_acc1[i];
        a.x *= d; a.y *= d; a.z *= d; a.w *= d;
        float g0 = 0.f, g1 = 0.f, g2 = 0.f, g3 = 0.f;
        #pragma unroll
        for (int j = 0; j < 64; j++) {
            float h = sB1[j];
            h = fmaf(a.x, sW1[j],       h);
            h = fmaf(a.y, sW1[64 + j],  h);
            h = fmaf(a.z, sW1[128 + j], h);
            h = fmaf(a.w, sW1[192 + j], h);
            h = fmaxf(h, 0.0f);
            g0 = fmaf(h, sW2[j * 4 + 0], g0);
            g1 = fmaf(h, sW2[j * 4 + 1], g1);
            g2 = fmaf(h, sW2[j * 4 + 2], g2);
            g3 = fmaf(h, sW2[j * 4 + 3], g3);
        }
        float4 gs = make_float4(g0 * d, g1 * d, g2 * d, g3 * d);
        g_gs[i]   = gs;
        g_acc2[i] = gs;
    }
}

// out = dinv * acc2 + b2
__global__ void k_final(const float* __restrict__ b2, float4* __restrict__ out, int n) {
    int i = blockIdx.x * blockDim.x + threadIdx.x;
    if (i < n) {
        float d = g_dinv[i];
        float4 a = g_acc2[i];
        float4 o;
        o.x = fmaf(d, a.x, b2[0]);
        o.y = fmaf(d, a.y, b2[1]);
        o.z = fmaf(d, a.z, b2[2]);
        o.w = fmaf(d, a.w, b2[3]);
        out[i] = o;
    }
}

extern "C" void kernel_launch(void* const* d_in, const int* in_sizes, int n_in,
                              void* d_out, int out_size) {
    const float* x  = (const float*)d_in[0];
    const int*   ei = (const int*)  d_in[1];
    const float* W1 = (const float*)d_in[2];
    const float* b1 = (const float*)d_in[3];
    const float* W2 = (const float*)d_in[4];
    const float* b2 = (const float*)d_in[5];

    int n = in_sizes[0] / 4;   // N nodes (S=4)
    int e = in_sizes[1] / 2;   // E edges
    const int* row = ei;
    const int* col = ei + e;

    void *p_xs, *p_acc1, *p_gs, *p_acc2;
    cudaGetSymbolAddress(&p_xs,   g_xs);
    cudaGetSymbolAddress(&p_acc1, g_acc1);
    cudaGetSymbolAddress(&p_gs,   g_gs);
    cudaGetSymbolAddress(&p_acc2, g_acc2);

    const int TB = 256;
    int nb_n  = (n + TB - 1) / TB;
    int nt_e  = (e + 3) / 4;               // edge threads (4 edges each)
    int nb_e  = (nt_e + TB - 1) / TB;

    k_deg_init <<<nb_n, TB>>>(n);
    k_deg_count<<<nb_e, TB>>>(col, e);
    k_node_pre <<<nb_n, TB>>>((const float4*)x, n);
    k_scatter  <<<nb_e, TB>>>(row, col, (const float4*)p_xs, (float4*)p_acc1, e);
    k_mlp      <<<nb_n, TB>>>(W1, b1, W2, n);
    k_scatter  <<<nb_e, TB>>>(row, col, (const float4*)p_gs, (float4*)p_acc2, e);
    k_final    <<<nb_n, TB>>>(b2, (float4*)d_out, n);
}